// round 4
// baseline (speedup 1.0000x reference)
#include <cuda_runtime.h>
#include <math.h>

#define BB   4
#define MM   8
#define NPTS 4096
#define HH   256
#define FDIM 512
#define SSEG 128
#define NSEG (BB*SSEG+1)
#define STR  20          // smem tile stride in floats (80B: 16B-aligned row-pairs)

typedef unsigned long long ull;

// -------- device scratch (no allocations allowed) --------
__device__ float g_pp[BB*NPTS*HH];        // relu(LN(PF@pW)) per point
__device__ float g_ppa[BB*NPTS*HH];       // pp @ a1_W_top (view-invariant half)
__device__ float g_attn[BB*MM*NPTS];      // sigmoid attention, layout (b,m,p)
__device__ float g_nattn[BB*NPTS*MM];     // softmax-normalized, layout (b,p,m)
__device__ float g_wvp[BB*NPTS*HH];       // relu(LN(weighted@vW))
__device__ float g_cnt[NSEG];
__device__ float g_asum[NSEG*MM];
__device__ float g_fsum[NSEG*HH];

// -------- packed f32x2 helpers (2x FMA throughput vs 3-reg FFMA) --------
__device__ __forceinline__ ull pack2(float lo, float hi){
    ull r; asm("mov.b64 %0, {%1,%2};" : "=l"(r) : "f"(lo), "f"(hi)); return r;
}
__device__ __forceinline__ void unpack2(ull v, float& lo, float& hi){
    asm("mov.b64 {%0,%1}, %2;" : "=f"(lo), "=f"(hi) : "l"(v));
}
__device__ __forceinline__ void fma2(ull& d, ull a, ull b){
    asm("fma.rn.f32x2 %0, %1, %2, %3;" : "=l"(d) : "l"(a), "l"(b), "l"(d));
}

// Row LN statistics over HH=256 columns for 16 rows staged in smem (stride STR).
// 8 warps, warp w handles rows 2w, 2w+1.
__device__ __forceinline__ void row_stats_16(const float* vt, float* rmean, float* rrstd){
    int tid = threadIdx.x, w = tid >> 5, lane = tid & 31;
    #pragma unroll
    for (int rr = 0; rr < 2; rr++){
        int r = 2*w + rr;
        float s = 0.f, q = 0.f;
        #pragma unroll
        for (int c = lane; c < HH; c += 32){ float v = vt[c*STR + r]; s += v; q += v*v; }
        #pragma unroll
        for (int o = 16; o; o >>= 1){
            s += __shfl_xor_sync(0xffffffffu, s, o);
            q += __shfl_xor_sync(0xffffffffu, q, o);
        }
        if (lane == 0){
            float m = s * (1.f/HH);
            float var = q * (1.f/HH) - m*m;
            rmean[r] = m; rrstd[r] = rsqrtf(var + 1e-5f);
        }
    }
}

// 16-row x 256-col GEMM slice: thread owns column tid, accumulates 8 row-pairs.
// xt: smem tile transposed [k][r], stride STR floats, 16B-aligned k-rows.
// Inner loop: 1 LDG + 1 pack + 4 LDS.128 + 8 FFMA2 -> fma-pipe-bound.
__device__ __forceinline__ void gemm16(const float* xt, const float* __restrict__ W,
                                       int ldw, ull acc[8]){
    int tid = threadIdx.x;
    #pragma unroll 4
    for (int k = 0; k < HH; k++){
        float w = W[k*ldw + tid];
        ull w2 = pack2(w, w);
        const ulonglong2* xp = (const ulonglong2*)(xt + k*STR);
        #pragma unroll
        for (int j = 0; j < 4; j++){
            ulonglong2 v = xp[j];
            fma2(acc[2*j    ], v.x, w2);
            fma2(acc[2*j + 1], v.y, w2);
        }
    }
}

// ============ Kernel A: pp = relu(LN(PF@pW+pb)); ppa = pp @ a1W_top ============
__global__ void __launch_bounds__(256) k_pp(const float* __restrict__ pf,
    const float* __restrict__ pW, const float* __restrict__ pb,
    const float* __restrict__ pg, const float* __restrict__ pbe,
    const float* __restrict__ a1W)
{
    __shared__ __align__(16) float xt[HH*STR];
    __shared__ __align__(16) float vt[HH*STR];
    __shared__ float rmean[16], rrstd[16];
    int tid = threadIdx.x;
    int row0 = blockIdx.x * 16;

    #pragma unroll
    for (int r = 0; r < 16; r++) xt[tid*STR + r] = pf[(row0 + r)*HH + tid];
    __syncthreads();

    ull acc[8];
    #pragma unroll
    for (int j = 0; j < 8; j++) acc[j] = 0ull;
    gemm16(xt, pW, HH, acc);

    float y[16]; float bias = pb[tid];
    #pragma unroll
    for (int j = 0; j < 8; j++) unpack2(acc[j], y[2*j], y[2*j+1]);
    #pragma unroll
    for (int r = 0; r < 16; r++){ y[r] += bias; vt[tid*STR + r] = y[r]; }
    __syncthreads();
    row_stats_16(vt, rmean, rrstd);
    __syncthreads();

    float gg = pg[tid], bb = pbe[tid];
    #pragma unroll
    for (int r = 0; r < 16; r++){
        float v = fmaxf((y[r] - rmean[r]) * rrstd[r] * gg + bb, 0.f);
        vt[tid*STR + r] = v;
        g_pp[(row0 + r)*HH + tid] = v;
    }
    __syncthreads();

    #pragma unroll
    for (int j = 0; j < 8; j++) acc[j] = 0ull;
    gemm16(vt, a1W, HH, acc);   // a1W rows [0,256) = pp half
    #pragma unroll
    for (int j = 0; j < 8; j++){
        float lo, hi; unpack2(acc[j], lo, hi);
        g_ppa[(row0 + 2*j    )*HH + tid] = lo;
        g_ppa[(row0 + 2*j + 1)*HH + tid] = hi;
    }
}

// ===== Kernel B (dominant): vp -> h -> attn, fully fused per 16 view-rows =====
__global__ void __launch_bounds__(256) k_attn(const float* __restrict__ vf,
    const float* __restrict__ vW, const float* __restrict__ vb,
    const float* __restrict__ vg, const float* __restrict__ vbe,
    const float* __restrict__ a1W, const float* __restrict__ a1b,
    const float* __restrict__ ag, const float* __restrict__ abe,
    const float* __restrict__ a2W, const float* __restrict__ a2b)
{
    __shared__ __align__(16) float xt[HH*STR];
    __shared__ __align__(16) float vt[HH*STR];
    __shared__ float rmean[16], rrstd[16];
    __shared__ float wpart[8][16];
    int tid = threadIdx.x;
    int row0 = blockIdx.x * 16;           // global (b,m,p) row
    int bm = row0 / NPTS, b = bm / MM, p0 = row0 % NPTS;

    #pragma unroll
    for (int r = 0; r < 16; r++) xt[tid*STR + r] = vf[(row0 + r)*HH + tid];

    // ---- prefetch phase-2 accumulator init (g_ppa + a1b) early: its DRAM/L2
    // latency is hidden behind the entire phase-1 GEMM (~3600 cyc) ----
    ull pacc[8];
    {
        float a1bias = a1b[tid];
        int ppr = b*NPTS + p0;
        #pragma unroll
        for (int j = 0; j < 8; j++){
            float lo = g_ppa[(ppr + 2*j    )*HH + tid] + a1bias;
            float hi = g_ppa[(ppr + 2*j + 1)*HH + tid] + a1bias;
            pacc[j] = pack2(lo, hi);
        }
    }
    __syncthreads();

    // ---- phase 1: vp = relu(LN(x@vW + vb)) ----
    ull acc[8];
    #pragma unroll
    for (int j = 0; j < 8; j++) acc[j] = 0ull;
    gemm16(xt, vW, HH, acc);

    float y[16]; float bias = vb[tid];
    #pragma unroll
    for (int j = 0; j < 8; j++) unpack2(acc[j], y[2*j], y[2*j+1]);
    #pragma unroll
    for (int r = 0; r < 16; r++){ y[r] += bias; vt[tid*STR + r] = y[r]; }
    __syncthreads();
    row_stats_16(vt, rmean, rrstd);
    __syncthreads();
    {
        float gg = vg[tid], bb = vbe[tid];
        #pragma unroll
        for (int r = 0; r < 16; r++){
            float v = fmaxf((y[r] - rmean[r]) * rrstd[r] * gg + bb, 0.f);
            vt[tid*STR + r] = v;
        }
    }
    __syncthreads();

    // ---- phase 2: h = relu(LN(ppa + vp@a1W_bot + a1b)) ----
    #pragma unroll
    for (int j = 0; j < 8; j++) acc[j] = pacc[j];
    gemm16(vt, a1W + HH*HH, HH, acc);   // a1W rows [256,512) = vp half

    #pragma unroll
    for (int j = 0; j < 8; j++) unpack2(acc[j], y[2*j], y[2*j+1]);
    #pragma unroll
    for (int r = 0; r < 16; r++) xt[tid*STR + r] = y[r];   // xt is dead, reuse for stats
    __syncthreads();
    row_stats_16(xt, rmean, rrstd);
    __syncthreads();

    // ---- attn = sigmoid(h . a2W + a2b), block reduction over 256 columns ----
    float gg = ag[tid], bb2 = abe[tid];
    float w2 = a2W[tid];
    float part[16];
    #pragma unroll
    for (int r = 0; r < 16; r++){
        float h = fmaxf((y[r] - rmean[r]) * rrstd[r] * gg + bb2, 0.f);
        part[r] = h * w2;
    }
    int w = tid >> 5, lane = tid & 31;
    #pragma unroll
    for (int r = 0; r < 16; r++){
        float s = part[r];
        #pragma unroll
        for (int o = 16; o; o >>= 1) s += __shfl_xor_sync(0xffffffffu, s, o);
        if (lane == 0) wpart[w][r] = s;
    }
    __syncthreads();
    if (tid < 16){
        float s = a2b[0];
        #pragma unroll
        for (int ww = 0; ww < 8; ww++) s += wpart[ww][tid];
        g_attn[row0 + tid] = 1.f / (1.f + expf(-s));
    }
}

// ============ Kernel: zero segment accumulators ============
__global__ void k_zero(){
    int i = blockIdx.x * blockDim.x + threadIdx.x;
    if (i < NSEG)      g_cnt[i]  = 0.f;
    if (i < NSEG*MM)   g_asum[i] = 0.f;
    if (i < NSEG*HH)   g_fsum[i] = 0.f;
}

// ============ Kernel: segment sums (warp per point) ============
__global__ void __launch_bounds__(256) k_seg(const int* __restrict__ sp){
    int w = threadIdx.x >> 5, lane = threadIdx.x & 31;
    int idx = blockIdx.x * 8 + w;               // b*NPTS + p
    int b = idx / NPTS, p = idx % NPTS;
    int s = sp[idx];
    if (s < 0) return;                           // warp-uniform
    int seg = b*SSEG + s;
    if (lane == 0) atomicAdd(&g_cnt[seg], 1.f);
    if (lane < MM) atomicAdd(&g_asum[seg*MM + lane], g_attn[(b*MM + lane)*NPTS + p]);
    #pragma unroll
    for (int d = lane; d < HH; d += 32) atomicAdd(&g_fsum[seg*HH + d], g_pp[idx*HH + d]);
}

// ====== Kernel: refine (cosine-sim blend) + softmax over M (warp per point) ======
__global__ void __launch_bounds__(256) k_refine(const int* __restrict__ sp){
    int w = threadIdx.x >> 5, lane = threadIdx.x & 31;
    int idx = blockIdx.x * 8 + w;
    int b = idx / NPTS, p = idx % NPTS;
    int s = sp[idx];
    bool valid = (s >= 0);
    int seg = valid ? (b*SSEG + s) : (BB*SSEG);
    float inv = 1.f / fmaxf(g_cnt[seg], 1.f);

    float dot = 0.f, n1 = 0.f, n2 = 0.f;
    for (int d = lane; d < HH; d += 32){
        float f  = g_pp[idx*HH + d];
        float fm = g_fsum[seg*HH + d] * inv;
        dot += f*fm; n1 += f*f; n2 += fm*fm;
    }
    #pragma unroll
    for (int o = 16; o; o >>= 1){
        dot += __shfl_xor_sync(0xffffffffu, dot, o);
        n1  += __shfl_xor_sync(0xffffffffu, n1,  o);
        n2  += __shfl_xor_sync(0xffffffffu, n2,  o);
    }
    float sim = dot / (fmaxf(sqrtf(n1), 1e-8f) * fmaxf(sqrtf(n2), 1e-8f));

    float ref = -1e30f;
    if (lane < MM){
        float a  = g_attn[(b*MM + lane)*NPTS + p];
        float am = g_asum[seg*MM + lane] * inv;
        ref = valid ? (am + (a - am) * sim) : a;
    }
    // softmax over lanes 0..7 (xor<8 stays within the group)
    float mx = ref;
    #pragma unroll
    for (int o = 4; o; o >>= 1) mx = fmaxf(mx, __shfl_xor_sync(0xffffffffu, mx, o));
    float e = (lane < MM) ? expf(ref - mx) : 0.f;
    float ssum = e;
    #pragma unroll
    for (int o = 4; o; o >>= 1) ssum += __shfl_xor_sync(0xffffffffu, ssum, o);
    if (lane < MM) g_nattn[idx*MM + lane] = e / ssum;
}

// ====== Kernel: wvp = relu(LN((sum_m nattn*vf) @ vW + vb))  [k_weighted fused in] ======
__global__ void __launch_bounds__(256) k_wvp(const float* __restrict__ vf,
    const float* __restrict__ vW, const float* __restrict__ vb,
    const float* __restrict__ vg, const float* __restrict__ vbe)
{
    __shared__ __align__(16) float xt[HH*STR];
    __shared__ float rmean[16], rrstd[16];
    int tid = threadIdx.x;
    int row0 = blockIdx.x * 16;               // b*NPTS + p0, b constant per block
    int b = row0 / NPTS, p0 = row0 % NPTS;

    // staging = weighted sum over views, computed on the fly (no g_weighted pass)
    #pragma unroll
    for (int r = 0; r < 16; r++){
        int p = p0 + r;
        const float* vfp = vf + ((size_t)(b*MM)*NPTS + p)*HH + tid;
        const float* na  = g_nattn + (row0 + r)*MM;
        float accw = 0.f;
        #pragma unroll
        for (int m = 0; m < MM; m++)
            accw += na[m] * vfp[(size_t)m*NPTS*HH];
        xt[tid*STR + r] = accw;
    }
    __syncthreads();

    ull acc[8];
    #pragma unroll
    for (int j = 0; j < 8; j++) acc[j] = 0ull;
    gemm16(xt, vW, HH, acc);
    __syncthreads();                           // all gemm reads of xt done

    float y[16]; float bias = vb[tid];
    #pragma unroll
    for (int j = 0; j < 8; j++) unpack2(acc[j], y[2*j], y[2*j+1]);
    #pragma unroll
    for (int r = 0; r < 16; r++){ y[r] += bias; xt[tid*STR + r] = y[r]; }
    __syncthreads();
    row_stats_16(xt, rmean, rrstd);
    __syncthreads();

    float gg = vg[tid], bb = vbe[tid];
    #pragma unroll
    for (int r = 0; r < 16; r++)
        g_wvp[(row0 + r)*HH + tid] = fmaxf((y[r] - rmean[r]) * rrstd[r] * gg + bb, 0.f);
}

// ====== Kernel: Z = LN(pp@fW_top + wvp@fW_bot + fb) -> out [B,NP,FD] ======
__global__ void __launch_bounds__(256) k_final(const float* __restrict__ fW,
    const float* __restrict__ fb, const float* __restrict__ fg,
    const float* __restrict__ fbe, float* __restrict__ out)
{
    __shared__ __align__(16) float xt[HH*STR];
    __shared__ float wps[8][16], wpq[8][16];
    __shared__ float rmean[16], rrstd[16];
    int tid = threadIdx.x;
    int row0 = blockIdx.x * 16;

    ull acc0[8], acc1[8];
    #pragma unroll
    for (int j = 0; j < 8; j++){ acc0[j] = 0ull; acc1[j] = 0ull; }

    // pass 1: pp half
    #pragma unroll
    for (int r = 0; r < 16; r++) xt[tid*STR + r] = g_pp[(row0 + r)*HH + tid];
    __syncthreads();
    {
        #pragma unroll 2
        for (int k = 0; k < HH; k++){
            float w0 = fW[k*FDIM + tid], w1 = fW[k*FDIM + tid + HH];
            ull w20 = pack2(w0, w0), w21 = pack2(w1, w1);
            const ulonglong2* xp = (const ulonglong2*)(xt + k*STR);
            #pragma unroll
            for (int j = 0; j < 4; j++){
                ulonglong2 v = xp[j];
                fma2(acc0[2*j], v.x, w20);  fma2(acc0[2*j+1], v.y, w20);
                fma2(acc1[2*j], v.x, w21);  fma2(acc1[2*j+1], v.y, w21);
            }
        }
    }
    __syncthreads();
    // pass 2: wvp half
    #pragma unroll
    for (int r = 0; r < 16; r++) xt[tid*STR + r] = g_wvp[(row0 + r)*HH + tid];
    __syncthreads();
    {
        #pragma unroll 2
        for (int k = 0; k < HH; k++){
            float w0 = fW[(k + HH)*FDIM + tid], w1 = fW[(k + HH)*FDIM + tid + HH];
            ull w20 = pack2(w0, w0), w21 = pack2(w1, w1);
            const ulonglong2* xp = (const ulonglong2*)(xt + k*STR);
            #pragma unroll
            for (int j = 0; j < 4; j++){
                ulonglong2 v = xp[j];
                fma2(acc0[2*j], v.x, w20);  fma2(acc0[2*j+1], v.y, w20);
                fma2(acc1[2*j], v.x, w21);  fma2(acc1[2*j+1], v.y, w21);
            }
        }
    }

    float y0[16], y1[16];
    float b0 = fb[tid], b1 = fb[tid + HH];
    #pragma unroll
    for (int j = 0; j < 8; j++){
        unpack2(acc0[j], y0[2*j], y0[2*j+1]);
        unpack2(acc1[j], y1[2*j], y1[2*j+1]);
    }
    #pragma unroll
    for (int r = 0; r < 16; r++){ y0[r] += b0; y1[r] += b1; }

    // LN over FD=512: shuffle-based block reduction (2 cols per thread)
    int w = tid >> 5, lane = tid & 31;
    #pragma unroll
    for (int r = 0; r < 16; r++){
        float s = y0[r] + y1[r];
        float q = y0[r]*y0[r] + y1[r]*y1[r];
        #pragma unroll
        for (int o = 16; o; o >>= 1){
            s += __shfl_xor_sync(0xffffffffu, s, o);
            q += __shfl_xor_sync(0xffffffffu, q, o);
        }
        if (lane == 0){ wps[w][r] = s; wpq[w][r] = q; }
    }
    __syncthreads();
    if (tid < 16){
        float s = 0.f, q = 0.f;
        #pragma unroll
        for (int ww = 0; ww < 8; ww++){ s += wps[ww][tid]; q += wpq[ww][tid]; }
        float m = s * (1.f/FDIM);
        float var = q * (1.f/FDIM) - m*m;
        rmean[tid] = m; rrstd[tid] = rsqrtf(var + 1e-5f);
    }
    __syncthreads();

    float g0 = fg[tid], g1 = fg[tid + HH], be0 = fbe[tid], be1 = fbe[tid + HH];
    #pragma unroll
    for (int r = 0; r < 16; r++){
        float m = rmean[r], rs = rrstd[r];
        out[(row0 + r)*FDIM + tid     ] = (y0[r] - m) * rs * g0 + be0;
        out[(row0 + r)*FDIM + tid + HH] = (y1[r] - m) * rs * g1 + be1;
    }
}

// ============================== launch ==============================
extern "C" void kernel_launch(void* const* d_in, const int* in_sizes, int n_in,
                              void* d_out, int out_size)
{
    (void)in_sizes; (void)n_in; (void)out_size;
    const float* pf   = (const float*)d_in[0];
    const float* vf   = (const float*)d_in[1];
    const int*   sp   = (const int*)  d_in[2];
    const float* pW   = (const float*)d_in[3];
    const float* pb   = (const float*)d_in[4];
    const float* pg   = (const float*)d_in[5];
    const float* pbe  = (const float*)d_in[6];
    const float* vW   = (const float*)d_in[7];
    const float* vb   = (const float*)d_in[8];
    const float* vg   = (const float*)d_in[9];
    const float* vbe  = (const float*)d_in[10];
    const float* a1W  = (const float*)d_in[11];
    const float* a1b  = (const float*)d_in[12];
    const float* ag   = (const float*)d_in[13];
    const float* abe  = (const float*)d_in[14];
    const float* a2W  = (const float*)d_in[15];
    const float* a2b  = (const float*)d_in[16];
    const float* fW   = (const float*)d_in[17];
    const float* fb   = (const float*)d_in[18];
    const float* fg   = (const float*)d_in[19];
    const float* fbe  = (const float*)d_in[20];
    float* out = (float*)d_out;

    k_zero   <<<(NSEG*HH + 255)/256, 256>>>();
    k_pp     <<<(BB*NPTS)/16, 256>>>(pf, pW, pb, pg, pbe, a1W);
    k_attn   <<<(BB*MM*NPTS)/16, 256>>>(vf, vW, vb, vg, vbe, a1W, a1b, ag, abe, a2W, a2b);
    k_seg    <<<(BB*NPTS)/8, 256>>>(sp);
    k_refine <<<(BB*NPTS)/8, 256>>>(sp);
    k_wvp    <<<(BB*NPTS)/16, 256>>>(vf, vW, vb, vg, vbe);
    k_final  <<<(BB*NPTS)/16, 256>>>(fW, fb, fg, fbe, out);
}

// round 6
// speedup vs baseline: 1.2433x; 1.2433x over previous
#include <cuda_runtime.h>
#include <cuda_bf16.h>
#include <math.h>

#define BB   4
#define MM   8
#define NPTS 4096
#define HH   256
#define FDIM 512
#define SSEG 128
#define NSEG (BB*SSEG+1)
#define STR  20          // smem tile stride (floats) for scalar kernels

typedef unsigned long long ull;
typedef unsigned int u32;

// -------- device scratch --------
__device__ float g_pp[BB*NPTS*HH];
__device__ float g_ppa[BB*NPTS*HH];
__device__ float g_attn[BB*MM*NPTS];
__device__ float g_nattn[BB*NPTS*MM];
__device__ float g_wvp[BB*NPTS*HH];
__device__ float g_cnt[NSEG];
__device__ float g_asum[NSEG*MM];
__device__ float g_fsum[NSEG*HH];
// split-bf16 weights in k-slice-blocked layout: [ks][n][16]  (ks = k/16)
__device__ __nv_bfloat16 g_vwh[HH*HH], g_vwl[HH*HH];
__device__ __nv_bfloat16 g_awh[HH*HH], g_awl[HH*HH];

// -------- f32x2 helpers (scalar kernels) --------
__device__ __forceinline__ ull pack2(float lo, float hi){
    ull r; asm("mov.b64 %0, {%1,%2};" : "=l"(r) : "f"(lo), "f"(hi)); return r;
}
__device__ __forceinline__ void unpack2(ull v, float& lo, float& hi){
    asm("mov.b64 {%0,%1}, %2;" : "=f"(lo), "=f"(hi) : "l"(v));
}
__device__ __forceinline__ void fma2(ull& d, ull a, ull b){
    asm("fma.rn.f32x2 %0, %1, %2, %3;" : "=l"(d) : "l"(a), "l"(b), "l"(d));
}

__device__ __forceinline__ void row_stats_16(const float* vt, float* rmean, float* rrstd){
    int tid = threadIdx.x, w = tid >> 5, lane = tid & 31;
    #pragma unroll
    for (int rr = 0; rr < 2; rr++){
        int r = 2*w + rr;
        float s = 0.f, q = 0.f;
        #pragma unroll
        for (int c = lane; c < HH; c += 32){ float v = vt[c*STR + r]; s += v; q += v*v; }
        #pragma unroll
        for (int o = 16; o; o >>= 1){
            s += __shfl_xor_sync(0xffffffffu, s, o);
            q += __shfl_xor_sync(0xffffffffu, q, o);
        }
        if (lane == 0){
            float m = s * (1.f/HH);
            float var = q * (1.f/HH) - m*m;
            rmean[r] = m; rrstd[r] = rsqrtf(var + 1e-5f);
        }
    }
}

__device__ __forceinline__ void gemm16(const float* xt, const float* __restrict__ W,
                                       int ldw, ull acc[8]){
    int tid = threadIdx.x;
    float w = __ldg(&W[tid]);
    #pragma unroll 4
    for (int k = 0; k < HH; k++){
        ull w2 = pack2(w, w);
        if (k + 1 < HH) w = __ldg(&W[(k+1)*ldw + tid]);
        const ulonglong2* xp = (const ulonglong2*)(xt + k*STR);
        #pragma unroll
        for (int j = 0; j < 4; j++){
            ulonglong2 v = xp[j];
            fma2(acc[2*j    ], v.x, w2);
            fma2(acc[2*j + 1], v.y, w2);
        }
    }
}

// ============ prep: split vW and a1W(bottom) into bf16 hi/lo, k-slice blocked ============
__global__ void __launch_bounds__(256) k_prep(const float* __restrict__ vW,
                                              const float* __restrict__ a1W){
    int idx = blockIdx.x*256 + threadIdx.x;   // k*256 + n
    int k = idx >> 8, n = idx & 255;
    int o = ((k >> 4)*256 + n)*16 + (k & 15);
    float v = vW[idx];
    __nv_bfloat16 vh = __float2bfloat16(v);
    g_vwh[o] = vh;
    g_vwl[o] = __float2bfloat16(v - __bfloat162float(vh));
    float a = a1W[(HH + k)*HH + n];           // bottom half rows [256,512)
    __nv_bfloat16 ah = __float2bfloat16(a);
    g_awh[o] = ah;
    g_awl[o] = __float2bfloat16(a - __bfloat162float(ah));
}

// ============ Kernel A (scalar): pp + ppa ============
__global__ void __launch_bounds__(256) k_pp(const float* __restrict__ pf,
    const float* __restrict__ pW, const float* __restrict__ pb,
    const float* __restrict__ pg, const float* __restrict__ pbe,
    const float* __restrict__ a1W)
{
    __shared__ __align__(16) float xt[HH*STR];
    __shared__ __align__(16) float vt[HH*STR];
    __shared__ float rmean[16], rrstd[16];
    int tid = threadIdx.x;
    int row0 = blockIdx.x * 16;

    #pragma unroll
    for (int r = 0; r < 16; r++) xt[tid*STR + r] = pf[(row0 + r)*HH + tid];
    __syncthreads();

    ull acc[8];
    #pragma unroll
    for (int j = 0; j < 8; j++) acc[j] = 0ull;
    gemm16(xt, pW, HH, acc);

    float y[16]; float bias = pb[tid];
    #pragma unroll
    for (int j = 0; j < 8; j++) unpack2(acc[j], y[2*j], y[2*j+1]);
    #pragma unroll
    for (int r = 0; r < 16; r++){ y[r] += bias; vt[tid*STR + r] = y[r]; }
    __syncthreads();
    row_stats_16(vt, rmean, rrstd);
    __syncthreads();

    float gg = pg[tid], bb = pbe[tid];
    #pragma unroll
    for (int r = 0; r < 16; r++){
        float v = fmaxf((y[r] - rmean[r]) * rrstd[r] * gg + bb, 0.f);
        vt[tid*STR + r] = v;
        g_pp[(row0 + r)*HH + tid] = v;
    }
    __syncthreads();

    #pragma unroll
    for (int j = 0; j < 8; j++) acc[j] = 0ull;
    gemm16(vt, a1W, HH, acc);   // a1W rows [0,256) = pp half
    #pragma unroll
    for (int j = 0; j < 8; j++){
        float lo, hi; unpack2(acc[j], lo, hi);
        g_ppa[(row0 + 2*j    )*HH + tid] = lo;
        g_ppa[(row0 + 2*j + 1)*HH + tid] = hi;
    }
}

// ======================= tensor-core k_attn =======================
// block: 64 rows x 256 cols, 256 threads = 8 warps = 4 row-strips x 2 col-groups.
// mma.m16n8k16 bf16, split-bf16 (3 products) for fp32-grade accuracy.
__device__ __forceinline__ void mma16816(float* c, u32 a0, u32 a1, u32 a2, u32 a3,
                                         u32 b0, u32 b1){
    asm volatile(
        "mma.sync.aligned.m16n8k16.row.col.f32.bf16.bf16.f32 "
        "{%0,%1,%2,%3}, {%4,%5,%6,%7}, {%8,%9}, {%0,%1,%2,%3};"
        : "+f"(c[0]), "+f"(c[1]), "+f"(c[2]), "+f"(c[3])
        : "r"(a0), "r"(a1), "r"(a2), "r"(a3), "r"(b0), "r"(b1));
}

#define XLD 264   // bf16 stride of A tiles (rows 64)  -> banks 4g+t, conflict-free
#define YLD 258   // f32 stride of Y/H tiles (even for float2 alignment)
#define WLD 24    // bf16 stride of W slice rows       -> banks 12g+t, conflict-free

// one GEMM phase: acc += Ah*(Wh+Wl) + Al*Wh over K=256 in 16 k-slices
__device__ __forceinline__ void mma_phase(
    const __nv_bfloat16* sAh, const __nv_bfloat16* sAl,
    const __nv_bfloat16* __restrict__ gWh, const __nv_bfloat16* __restrict__ gWl,
    __nv_bfloat16* sWh, __nv_bfloat16* sWl, float* acc, int tid)
{
    const int lane = tid & 31, wid = tid >> 5;
    const int g = lane >> 2, t = lane & 3;
    const int rb  = (wid >> 1) * 16;
    const int cgo = (wid & 1) * 128;
    for (int ks = 0; ks < 16; ks++){
        __syncthreads();                       // previous slice fully consumed / A ready
        {   // stage W k-slice: thread tid owns n=tid (32B hi + 32B lo, coalesced)
            const uint4* srcH = (const uint4*)(gWh + ks*4096 + tid*16);
            const uint4* srcL = (const uint4*)(gWl + ks*4096 + tid*16);
            uint4 h0 = srcH[0], h1 = srcH[1], l0 = srcL[0], l1 = srcL[1];
            uint4* dH = (uint4*)(sWh + tid*WLD);
            uint4* dL = (uint4*)(sWl + tid*WLD);
            dH[0] = h0; dH[1] = h1; dL[0] = l0; dL[1] = l1;
        }
        __syncthreads();
        const int k0 = ks*16;
        u32 A0h = *(const u32*)(sAh + (rb+g  )*XLD + k0 + 2*t);
        u32 A1h = *(const u32*)(sAh + (rb+g+8)*XLD + k0 + 2*t);
        u32 A2h = *(const u32*)(sAh + (rb+g  )*XLD + k0 + 2*t + 8);
        u32 A3h = *(const u32*)(sAh + (rb+g+8)*XLD + k0 + 2*t + 8);
        u32 A0l = *(const u32*)(sAl + (rb+g  )*XLD + k0 + 2*t);
        u32 A1l = *(const u32*)(sAl + (rb+g+8)*XLD + k0 + 2*t);
        u32 A2l = *(const u32*)(sAl + (rb+g  )*XLD + k0 + 2*t + 8);
        u32 A3l = *(const u32*)(sAl + (rb+g+8)*XLD + k0 + 2*t + 8);
        #pragma unroll
        for (int j = 0; j < 16; j++){
            int n = cgo + j*8 + g;
            u32 B0h = *(const u32*)(sWh + n*WLD + 2*t);
            u32 B1h = *(const u32*)(sWh + n*WLD + 2*t + 8);
            u32 B0l = *(const u32*)(sWl + n*WLD + 2*t);
            u32 B1l = *(const u32*)(sWl + n*WLD + 2*t + 8);
            float* c = acc + 4*j;
            mma16816(c, A0h,A1h,A2h,A3h, B0h,B1h);
            mma16816(c, A0h,A1h,A2h,A3h, B0l,B1l);
            mma16816(c, A0l,A1l,A2l,A3l, B0h,B1h);
        }
    }
    __syncthreads();
}

// dynamic smem layout
#define OFF_XH 0
#define OFF_XL (OFF_XH + 64*XLD*2)                 // 33792
#define OFF_Y  (OFF_XL + 64*XLD*2)                 // 67584
#define OFF_WH (OFF_Y  + 64*YLD*4)                 // 133632
#define OFF_WL (OFF_WH + 256*WLD*2)                // 145920
#define OFF_RM (OFF_WL + 256*WLD*2)                // 158208
#define OFF_RS (OFF_RM + 64*4)
#define OFF_WP (OFF_RS + 64*4)
#define SMEM_DYN (OFF_WP + 8*64*4)                 // 160768

__global__ void __launch_bounds__(256) k_attn_mma(const float* __restrict__ vf,
    const float* __restrict__ vb, const float* __restrict__ vg,
    const float* __restrict__ vbe, const float* __restrict__ a1b,
    const float* __restrict__ ag, const float* __restrict__ abe,
    const float* __restrict__ a2W, const float* __restrict__ a2b)
{
    extern __shared__ __align__(16) char sm[];
    __nv_bfloat16* sXh = (__nv_bfloat16*)(sm + OFF_XH);   // also VPh
    __nv_bfloat16* sXl = (__nv_bfloat16*)(sm + OFF_XL);   // also VPl
    float*         sY  = (float*)        (sm + OFF_Y);    // also H
    __nv_bfloat16* sWh = (__nv_bfloat16*)(sm + OFF_WH);
    __nv_bfloat16* sWl = (__nv_bfloat16*)(sm + OFF_WL);
    float* rm    = (float*)(sm + OFF_RM);
    float* rs    = (float*)(sm + OFF_RS);
    float* wpart = (float*)(sm + OFF_WP);                 // [8][64]

    const int tid = threadIdx.x;
    const int row0 = blockIdx.x * 64;                     // global (b,m,p) row
    const int b  = row0 >> 15;                            // / (MM*NPTS)
    const int p0 = row0 & (NPTS - 1);
    const int lane = tid & 31, wid = tid >> 5;
    const int g = lane >> 2, t = lane & 3;
    const int rb  = (wid >> 1) * 16;
    const int cgo = (wid & 1) * 128;

    // ---- stage X = vf rows, split to bf16 hi/lo ----
    #pragma unroll 4
    for (int r = 0; r < 64; r++){
        float x = vf[(size_t)(row0 + r)*HH + tid];
        __nv_bfloat16 h = __float2bfloat16(x);
        sXh[r*XLD + tid] = h;
        sXl[r*XLD + tid] = __float2bfloat16(x - __bfloat162float(h));
    }

    float acc[64];
    #pragma unroll
    for (int i = 0; i < 64; i++) acc[i] = 0.f;

    // ---- phase 1: Y = X @ vW ----
    mma_phase(sXh, sXl, g_vwh, g_vwl, sWh, sWl, acc, tid);

    // write Y + vb to smem
    #pragma unroll
    for (int j = 0; j < 16; j++){
        int c0 = cgo + j*8 + 2*t;
        float2 vb2 = *(const float2*)&vb[c0];
        float2 y0 = make_float2(acc[4*j]   + vb2.x, acc[4*j+1] + vb2.y);
        float2 y1 = make_float2(acc[4*j+2] + vb2.x, acc[4*j+3] + vb2.y);
        *(float2*)&sY[(rb+g  )*YLD + c0] = y0;
        *(float2*)&sY[(rb+g+8)*YLD + c0] = y1;
    }
    __syncthreads();

    // LN stats (warp w -> rows 8w..8w+7)
    #pragma unroll
    for (int rr = 0; rr < 8; rr++){
        int r = wid*8 + rr;
        float s = 0.f, q = 0.f;
        #pragma unroll
        for (int i = 0; i < 8; i++){ float v = sY[r*YLD + lane + 32*i]; s += v; q += v*v; }
        #pragma unroll
        for (int o = 16; o; o >>= 1){
            s += __shfl_xor_sync(0xffffffffu, s, o);
            q += __shfl_xor_sync(0xffffffffu, q, o);
        }
        if (lane == 0){
            float m = s * (1.f/HH);
            rm[r] = m; rs[r] = rsqrtf(q*(1.f/HH) - m*m + 1e-5f);
        }
    }
    __syncthreads();

    // VP = relu(LN(Y)) -> split bf16 into X buffers
    {
        float gg = vg[tid], bb = vbe[tid];
        #pragma unroll 4
        for (int r = 0; r < 64; r++){
            float v = fmaxf((sY[r*YLD + tid] - rm[r]) * rs[r] * gg + bb, 0.f);
            __nv_bfloat16 h = __float2bfloat16(v);
            sXh[r*XLD + tid] = h;
            sXl[r*XLD + tid] = __float2bfloat16(v - __bfloat162float(h));
        }
    }

    // acc init = ppa (pp @ a1W_top), fp32
    {
        int prow = b*NPTS + p0;
        #pragma unroll
        for (int j = 0; j < 16; j++){
            int c0 = cgo + j*8 + 2*t;
            float2 pa = *(const float2*)&g_ppa[(size_t)(prow + rb+g  )*HH + c0];
            float2 pc = *(const float2*)&g_ppa[(size_t)(prow + rb+g+8)*HH + c0];
            acc[4*j] = pa.x; acc[4*j+1] = pa.y; acc[4*j+2] = pc.x; acc[4*j+3] = pc.y;
        }
    }

    // ---- phase 2: H = ppa + VP @ a1W_bot ----  (first sync inside covers VP writes)
    mma_phase(sXh, sXl, g_awh, g_awl, sWh, sWl, acc, tid);

    // write H + a1b to smem
    #pragma unroll
    for (int j = 0; j < 16; j++){
        int c0 = cgo + j*8 + 2*t;
        float2 ab2 = *(const float2*)&a1b[c0];
        float2 h0 = make_float2(acc[4*j]   + ab2.x, acc[4*j+1] + ab2.y);
        float2 h1 = make_float2(acc[4*j+2] + ab2.x, acc[4*j+3] + ab2.y);
        *(float2*)&sY[(rb+g  )*YLD + c0] = h0;
        *(float2*)&sY[(rb+g+8)*YLD + c0] = h1;
    }
    __syncthreads();

    // stats for H
    #pragma unroll
    for (int rr = 0; rr < 8; rr++){
        int r = wid*8 + rr;
        float s = 0.f, q = 0.f;
        #pragma unroll
        for (int i = 0; i < 8; i++){ float v = sY[r*YLD + lane + 32*i]; s += v; q += v*v; }
        #pragma unroll
        for (int o = 16; o; o >>= 1){
            s += __shfl_xor_sync(0xffffffffu, s, o);
            q += __shfl_xor_sync(0xffffffffu, q, o);
        }
        if (lane == 0){
            float m = s * (1.f/HH);
            rm[r] = m; rs[r] = rsqrtf(q*(1.f/HH) - m*m + 1e-5f);
        }
    }
    __syncthreads();

    // attn = sigmoid(relu(LN(H)) . a2W + a2b)
    {
        float gg = ag[tid], bb = abe[tid], w2 = a2W[tid];
        for (int r = 0; r < 64; r++){
            float h = fmaxf((sY[r*YLD + tid] - rm[r]) * rs[r] * gg + bb, 0.f) * w2;
            #pragma unroll
            for (int o = 16; o; o >>= 1) h += __shfl_xor_sync(0xffffffffu, h, o);
            if (lane == 0) wpart[wid*64 + r] = h;
        }
    }
    __syncthreads();
    if (tid < 64){
        float s = a2b[0];
        #pragma unroll
        for (int ww = 0; ww < 8; ww++) s += wpart[ww*64 + tid];
        g_attn[row0 + tid] = 1.f / (1.f + expf(-s));
    }
}

// ============ zero / seg / refine (unchanged) ============
__global__ void k_zero(){
    int i = blockIdx.x * blockDim.x + threadIdx.x;
    if (i < NSEG)      g_cnt[i]  = 0.f;
    if (i < NSEG*MM)   g_asum[i] = 0.f;
    if (i < NSEG*HH)   g_fsum[i] = 0.f;
}

__global__ void __launch_bounds__(256) k_seg(const int* __restrict__ sp){
    int w = threadIdx.x >> 5, lane = threadIdx.x & 31;
    int idx = blockIdx.x * 8 + w;
    int b = idx / NPTS, p = idx % NPTS;
    int s = sp[idx];
    if (s < 0) return;
    int seg = b*SSEG + s;
    if (lane == 0) atomicAdd(&g_cnt[seg], 1.f);
    if (lane < MM) atomicAdd(&g_asum[seg*MM + lane], g_attn[(b*MM + lane)*NPTS + p]);
    #pragma unroll
    for (int d = lane; d < HH; d += 32) atomicAdd(&g_fsum[seg*HH + d], g_pp[idx*HH + d]);
}

__global__ void __launch_bounds__(256) k_refine(const int* __restrict__ sp){
    int w = threadIdx.x >> 5, lane = threadIdx.x & 31;
    int idx = blockIdx.x * 8 + w;
    int b = idx / NPTS, p = idx % NPTS;
    int s = sp[idx];
    bool valid = (s >= 0);
    int seg = valid ? (b*SSEG + s) : (BB*SSEG);
    float inv = 1.f / fmaxf(g_cnt[seg], 1.f);

    float dot = 0.f, n1 = 0.f, n2 = 0.f;
    for (int d = lane; d < HH; d += 32){
        float f  = g_pp[idx*HH + d];
        float fm = g_fsum[seg*HH + d] * inv;
        dot += f*fm; n1 += f*f; n2 += fm*fm;
    }
    #pragma unroll
    for (int o = 16; o; o >>= 1){
        dot += __shfl_xor_sync(0xffffffffu, dot, o);
        n1  += __shfl_xor_sync(0xffffffffu, n1,  o);
        n2  += __shfl_xor_sync(0xffffffffu, n2,  o);
    }
    float sim = dot / (fmaxf(sqrtf(n1), 1e-8f) * fmaxf(sqrtf(n2), 1e-8f));

    float ref = -1e30f;
    if (lane < MM){
        float a  = g_attn[(b*MM + lane)*NPTS + p];
        float am = g_asum[seg*MM + lane] * inv;
        ref = valid ? (am + (a - am) * sim) : a;
    }
    float mx = ref;
    #pragma unroll
    for (int o = 4; o; o >>= 1) mx = fmaxf(mx, __shfl_xor_sync(0xffffffffu, mx, o));
    float e = (lane < MM) ? expf(ref - mx) : 0.f;
    float ssum = e;
    #pragma unroll
    for (int o = 4; o; o >>= 1) ssum += __shfl_xor_sync(0xffffffffu, ssum, o);
    if (lane < MM) g_nattn[idx*MM + lane] = e / ssum;
}

// ====== wvp (scalar, weighted sum fused) ======
__global__ void __launch_bounds__(256) k_wvp(const float* __restrict__ vf,
    const float* __restrict__ vW, const float* __restrict__ vb,
    const float* __restrict__ vg, const float* __restrict__ vbe)
{
    __shared__ __align__(16) float xt[HH*STR];
    __shared__ float rmean[16], rrstd[16];
    int tid = threadIdx.x;
    int row0 = blockIdx.x * 16;
    int b = row0 / NPTS, p0 = row0 % NPTS;

    #pragma unroll
    for (int r = 0; r < 16; r++){
        int p = p0 + r;
        const float* vfp = vf + ((size_t)(b*MM)*NPTS + p)*HH + tid;
        const float* na  = g_nattn + (row0 + r)*MM;
        float accw = 0.f;
        #pragma unroll
        for (int m = 0; m < MM; m++)
            accw += na[m] * vfp[(size_t)m*NPTS*HH];
        xt[tid*STR + r] = accw;
    }
    __syncthreads();

    ull acc[8];
    #pragma unroll
    for (int j = 0; j < 8; j++) acc[j] = 0ull;
    gemm16(xt, vW, HH, acc);
    __syncthreads();

    float y[16]; float bias = vb[tid];
    #pragma unroll
    for (int j = 0; j < 8; j++) unpack2(acc[j], y[2*j], y[2*j+1]);
    #pragma unroll
    for (int r = 0; r < 16; r++){ y[r] += bias; xt[tid*STR + r] = y[r]; }
    __syncthreads();
    row_stats_16(xt, rmean, rrstd);
    __syncthreads();

    float gg = vg[tid], bb = vbe[tid];
    #pragma unroll
    for (int r = 0; r < 16; r++)
        g_wvp[(row0 + r)*HH + tid] = fmaxf((y[r] - rmean[r]) * rrstd[r] * gg + bb, 0.f);
}

// ====== final (scalar) ======
__global__ void __launch_bounds__(256) k_final(const float* __restrict__ fW,
    const float* __restrict__ fb, const float* __restrict__ fg,
    const float* __restrict__ fbe, float* __restrict__ out)
{
    __shared__ __align__(16) float xt[HH*STR];
    __shared__ float wps[8][16], wpq[8][16];
    __shared__ float rmean[16], rrstd[16];
    int tid = threadIdx.x;
    int row0 = blockIdx.x * 16;

    ull acc0[8], acc1[8];
    #pragma unroll
    for (int j = 0; j < 8; j++){ acc0[j] = 0ull; acc1[j] = 0ull; }

    #pragma unroll
    for (int r = 0; r < 16; r++) xt[tid*STR + r] = g_pp[(row0 + r)*HH + tid];
    __syncthreads();
    {
        #pragma unroll 2
        for (int k = 0; k < HH; k++){
            float w0 = fW[k*FDIM + tid], w1 = fW[k*FDIM + tid + HH];
            ull w20 = pack2(w0, w0), w21 = pack2(w1, w1);
            const ulonglong2* xp = (const ulonglong2*)(xt + k*STR);
            #pragma unroll
            for (int j = 0; j < 4; j++){
                ulonglong2 v = xp[j];
                fma2(acc0[2*j], v.x, w20);  fma2(acc0[2*j+1], v.y, w20);
                fma2(acc1[2*j], v.x, w21);  fma2(acc1[2*j+1], v.y, w21);
            }
        }
    }
    __syncthreads();
    #pragma unroll
    for (int r = 0; r < 16; r++) xt[tid*STR + r] = g_wvp[(row0 + r)*HH + tid];
    __syncthreads();
    {
        #pragma unroll 2
        for (int k = 0; k < HH; k++){
            float w0 = fW[(k + HH)*FDIM + tid], w1 = fW[(k + HH)*FDIM + tid + HH];
            ull w20 = pack2(w0, w0), w21 = pack2(w1, w1);
            const ulonglong2* xp = (const ulonglong2*)(xt + k*STR);
            #pragma unroll
            for (int j = 0; j < 4; j++){
                ulonglong2 v = xp[j];
                fma2(acc0[2*j], v.x, w20);  fma2(acc0[2*j+1], v.y, w20);
                fma2(acc1[2*j], v.x, w21);  fma2(acc1[2*j+1], v.y, w21);
            }
        }
    }

    float y0[16], y1[16];
    float b0 = fb[tid], b1 = fb[tid + HH];
    #pragma unroll
    for (int j = 0; j < 8; j++){
        unpack2(acc0[j], y0[2*j], y0[2*j+1]);
        unpack2(acc1[j], y1[2*j], y1[2*j+1]);
    }
    #pragma unroll
    for (int r = 0; r < 16; r++){ y0[r] += b0; y1[r] += b1; }

    int w = tid >> 5, lane = tid & 31;
    #pragma unroll
    for (int r = 0; r < 16; r++){
        float s = y0[r] + y1[r];
        float q = y0[r]*y0[r] + y1[r]*y1[r];
        #pragma unroll
        for (int o = 16; o; o >>= 1){
            s += __shfl_xor_sync(0xffffffffu, s, o);
            q += __shfl_xor_sync(0xffffffffu, q, o);
        }
        if (lane == 0){ wps[w][r] = s; wpq[w][r] = q; }
    }
    __syncthreads();
    if (tid < 16){
        float s = 0.f, q = 0.f;
        #pragma unroll
        for (int ww = 0; ww < 8; ww++){ s += wps[ww][tid]; q += wpq[ww][tid]; }
        float m = s * (1.f/FDIM);
        float var = q * (1.f/FDIM) - m*m;
        rmean[tid] = m; rrstd[tid] = rsqrtf(var + 1e-5f);
    }
    __syncthreads();

    float g0 = fg[tid], g1 = fg[tid + HH], be0 = fbe[tid], be1 = fbe[tid + HH];
    #pragma unroll
    for (int r = 0; r < 16; r++){
        float m = rmean[r], rsd = rrstd[r];
        out[(row0 + r)*FDIM + tid     ] = (y0[r] - m) * rsd * g0 + be0;
        out[(row0 + r)*FDIM + tid + HH] = (y1[r] - m) * rsd * g1 + be1;
    }
}

// ============================== launch ==============================
// ncu captures OUR launch index 3 (-s 5 -c 1, 2 harness launches first).
// Order places k_attn_mma (dominant) at index 3.
extern "C" void kernel_launch(void* const* d_in, const int* in_sizes, int n_in,
                              void* d_out, int out_size)
{
    (void)in_sizes; (void)n_in; (void)out_size;
    const float* pf   = (const float*)d_in[0];
    const float* vf   = (const float*)d_in[1];
    const int*   sp   = (const int*)  d_in[2];
    const float* pW   = (const float*)d_in[3];
    const float* pb   = (const float*)d_in[4];
    const float* pg   = (const float*)d_in[5];
    const float* pbe  = (const float*)d_in[6];
    const float* vW   = (const float*)d_in[7];
    const float* vb   = (const float*)d_in[8];
    const float* vg   = (const float*)d_in[9];
    const float* vbe  = (const float*)d_in[10];
    const float* a1W  = (const float*)d_in[11];
    const float* a1b  = (const float*)d_in[12];
    const float* ag   = (const float*)d_in[13];
    const float* abe  = (const float*)d_in[14];
    const float* a2W  = (const float*)d_in[15];
    const float* a2b  = (const float*)d_in[16];
    const float* fW   = (const float*)d_in[17];
    const float* fb   = (const float*)d_in[18];
    const float* fg   = (const float*)d_in[19];
    const float* fbe  = (const float*)d_in[20];
    float* out = (float*)d_out;

    cudaFuncSetAttribute(k_attn_mma, cudaFuncAttributeMaxDynamicSharedMemorySize, SMEM_DYN);

    k_zero     <<<(NSEG*HH + 255)/256, 256>>>();                  // idx 0
    k_prep     <<<256, 256>>>(vW, a1W);                           // idx 1
    k_pp       <<<(BB*NPTS)/16, 256>>>(pf, pW, pb, pg, pbe, a1W); // idx 2
    k_attn_mma <<<(BB*MM*NPTS)/64, 256, SMEM_DYN>>>(vf, vb, vg, vbe, a1b, ag, abe, a2W, a2b); // idx 3 = captured
    k_seg      <<<(BB*NPTS)/8, 256>>>(sp);
    k_refine   <<<(BB*NPTS)/8, 256>>>(sp);
    k_wvp      <<<(BB*NPTS)/16, 256>>>(vf, vW, vb, vg, vbe);
    k_final    <<<(BB*NPTS)/16, 256>>>(fW, fb, fg, fbe, out);
}